// round 8
// baseline (speedup 1.0000x reference)
#include <cuda_runtime.h>
#include <cuda_fp16.h>
#include <cstdint>

// ----------------------------------------------------------------------------
// Problem constants
// ----------------------------------------------------------------------------
#define BS_      1024
#define KTOT     33154
#define HID      512
#define ODIM     129
#define ST_LEN   16641
#define AT_LEN_  129
#define ST1_LEN  16384
#define B_AT     16641      /* st | at boundary   */
#define B_ST1    16770      /* at | st1 boundary  */

#define MT       256        /* CTA tile M (batch)  */
#define NT       128        /* CTA tile N (hidden) */
#define CHUNK    64         /* K per stage (fp16)  */
#define NCHUNK   519        /* ceil(33154/64)      */
#define SPLIT    9
#define CPS      58         /* ceil(519/9)         */

#define A_BYTES  (MT * CHUNK * 2)          /* 32768 */
#define B_BYTES  (NT * CHUNK * 2)          /* 16384 */
#define STAGE    (A_BYTES + B_BYTES)       /* 49152 */
#define SMEM_TOTAL (1024 + 2 * STAGE)      /* 99328 */

// split-K partials: 9 * 1024 * 512 * 4 = 18.9 MB
__device__ float g_partial[SPLIT * BS_ * HID];
// W2 transposed: [129][512] floats
__device__ float g_w2t[ODIM * HID];

// ----------------------------------------------------------------------------
// Helpers (plain-sm_103-safe PTX: ldmatrix / mma.sync fp16 / cvt.rn.f16x2)
// ----------------------------------------------------------------------------
__device__ __forceinline__ uint32_t smem_u32(const void* p) {
    uint32_t a;
    asm("{ .reg .u64 t; cvta.to.shared.u64 t, %1; cvt.u32.u64 %0, t; }" : "=r"(a) : "l"(p));
    return a;
}

__device__ __forceinline__ uint32_t swz(uint32_t off) {
    return off ^ ((off >> 3) & 0x70u);
}

// pack two f32 -> f16x2 (lo = x, hi = y), round-to-nearest-even
__device__ __forceinline__ uint32_t pack_f16x2(float x, float y) {
    uint32_t r;
    asm("cvt.rn.f16x2.f32 %0, %1, %2;" : "=r"(r) : "f"(y), "f"(x));
    return r;
}

__device__ __forceinline__ void ldsm_x4(uint32_t r[4], uint32_t addr) {
    asm volatile("ldmatrix.sync.aligned.m8n8.x4.shared.b16 {%0,%1,%2,%3}, [%4];"
                 : "=r"(r[0]), "=r"(r[1]), "=r"(r[2]), "=r"(r[3]) : "r"(addr));
}

__device__ __forceinline__ void ldsm_x2(uint32_t r[2], uint32_t addr) {
    asm volatile("ldmatrix.sync.aligned.m8n8.x2.shared.b16 {%0,%1}, [%2];"
                 : "=r"(r[0]), "=r"(r[1]) : "r"(addr));
}

// fp16 MMA with fp16 accumulators (full-rate path on consumer-derived pipes)
__device__ __forceinline__ void mma_f16acc(uint32_t c[2], const uint32_t a[4], const uint32_t b[2]) {
    asm volatile(
        "mma.sync.aligned.m16n8k16.row.col.f16.f16.f16.f16 "
        "{%0,%1}, {%2,%3,%4,%5}, {%6,%7}, {%0,%1};"
        : "+r"(c[0]), "+r"(c[1])
        : "r"(a[0]), "r"(a[1]), "r"(a[2]), "r"(a[3]), "r"(b[0]), "r"(b[1]));
}

__device__ __forceinline__ void sts32(uint32_t addr, uint32_t v) {
    asm volatile("st.shared.b32 [%0], %1;" :: "r"(addr), "r"(v));
}
__device__ __forceinline__ void sts128(uint32_t addr, uint32_t v0, uint32_t v1, uint32_t v2, uint32_t v3) {
    asm volatile("st.shared.v4.b32 [%0], {%1,%2,%3,%4};" :: "r"(addr), "r"(v0), "r"(v1), "r"(v2), "r"(v3));
}

// ----------------------------------------------------------------------------
// GEMM1: H_partial = X @ W1, fp16 mma (f16 acc, per-chunk f32 dump), split-K=9.
// grid = 144 CTAs = 4 nt x 4 mt x 9 split, 512 threads (16 warps).
// SMEM per stage: A [256 m][64 k] fp16, B [128 n][64 k] fp16; 128B rows, SW128.
// Warp tile 64(M) x 32(N).
// ----------------------------------------------------------------------------
__global__ void __launch_bounds__(512, 1) gemm1_kernel(
    const float* __restrict__ st, const float* __restrict__ at,
    const float* __restrict__ st1, const float* __restrict__ W1)
{
    extern __shared__ char smem_raw[];
    uint32_t base = smem_u32(smem_raw);
    base = (base + 1023u) & ~1023u;

    const int tid = threadIdx.x;
    const int l   = tid & 31;
    const int w   = tid >> 5;
    const int wm  = w >> 2;       // 0..3
    const int wn  = w & 3;        // 0..3

    const int bx = blockIdx.x;
    const int nt = bx & 3;
    const int mt = (bx >> 2) & 3;
    const int sp = bx >> 4;       // 0..8

    const int c0  = sp * CPS;
    int nch = NCHUNK - c0;
    if (nch > CPS) nch = CPS;

    // A staging geometry: kp = tid&31 -> k pair (2*kp, 2*kp+1), rg = tid>>5 -> 16 rows
    const int kp = tid & 31;
    const int rg = tid >> 5;
    const int am_base = mt * MT + rg * 16;

    // B staging geometry: n = tid&127, kg = tid>>7 -> 16 k values
    const int bn  = tid & 127;
    const int bkg = tid >> 7;                 // 0..3
    const float* W1p = W1 + (size_t)(nt * NT + bn);

    // scalar X element
    auto loadX = [&](int m, int k) -> float {
        if (k < B_AT)   return __ldg(st  + (size_t)m * ST_LEN  + k);
        if (k < B_ST1)  return __ldg(at  + (size_t)m * AT_LEN_ + (k - B_AT));
        if (k < KTOT)   return __ldg(st1 + (size_t)m * ST1_LEN + (k - B_ST1));
        return 0.0f;
    };

    // load 8 rows (half of this thread's 16) of the k pair
    auto loadA = [&](int chunk, int half, float2 v[8]) {
        const int k = chunk * CHUNK + 2 * kp;
        const int m0 = am_base + half * 8;
#pragma unroll
        for (int r = 0; r < 8; ++r) {
            v[r].x = loadX(m0 + r, k);
            v[r].y = loadX(m0 + r, k + 1);
        }
    };
    auto storeA = [&](int s, int half, const float2 v[8]) {
        const uint32_t Ab = base + (uint32_t)s * STAGE;
#pragma unroll
        for (int r = 0; r < 8; ++r)
            sts32(Ab + swz((uint32_t)((rg * 16 + half * 8 + r) * 128 + kp * 4)),
                  pack_f16x2(v[r].x, v[r].y));
    };

    // B: 16 k values of column bn (transpose W1[k][n] -> smem[n][k])
    auto loadB = [&](int chunk, float bF[16]) {
        const int kb = chunk * CHUNK + bkg * 16;
#pragma unroll
        for (int j = 0; j < 16; ++j) {
            const int k = kb + j;
            bF[j] = (k < KTOT) ? __ldg(W1p + (size_t)k * HID) : 0.0f;
        }
    };
    auto storeB = [&](int s, const float bF[16]) {
        const uint32_t Bb = base + (uint32_t)s * STAGE + A_BYTES;
        uint32_t p0 = pack_f16x2(bF[0], bF[1]),  p1 = pack_f16x2(bF[2], bF[3]);
        uint32_t p2 = pack_f16x2(bF[4], bF[5]),  p3 = pack_f16x2(bF[6], bF[7]);
        sts128(Bb + swz((uint32_t)(bn * 128 + bkg * 32)), p0, p1, p2, p3);
        p0 = pack_f16x2(bF[8], bF[9]);   p1 = pack_f16x2(bF[10], bF[11]);
        p2 = pack_f16x2(bF[12], bF[13]); p3 = pack_f16x2(bF[14], bF[15]);
        sts128(Bb + swz((uint32_t)(bn * 128 + bkg * 32 + 16)), p0, p1, p2, p3);
    };

    // ---- fragment smem offsets (pre-swizzle, in-tile) ----
    uint32_t relA[4], relB[4];
#pragma unroll
    for (int t = 0; t < 4; ++t)
        relA[t] = (uint32_t)((wm * 64 + t * 16 + (l & 7) + ((l >> 3) & 1) * 8) * 128
                             + ((l >> 4) & 1) * 16);
    const int lm = l & 15;
#pragma unroll
    for (int u = 0; u < 4; ++u)
        relB[u] = (uint32_t)((wn * 32 + u * 8 + (lm & 7)) * 128 + ((lm >> 3) & 1) * 16);

    // fp32 master accumulators + per-chunk fp16 accumulators
    float    facc[4][4][4];
    uint32_t cacc[4][4][2];
#pragma unroll
    for (int t = 0; t < 4; ++t)
#pragma unroll
        for (int u = 0; u < 4; ++u) {
#pragma unroll
            for (int j = 0; j < 4; ++j) facc[t][u][j] = 0.0f;
            cacc[t][u][0] = 0u; cacc[t][u][1] = 0u;
        }

    // ---- prologue ----
    {
        float2 v[8]; float bF[16];
        loadA(c0, 0, v); storeA(0, 0, v);
        loadA(c0, 1, v); storeA(0, 1, v);
        loadB(c0, bF);   storeB(0, bF);
    }
    __syncthreads();

    // ---- main loop ----
    for (int i = 0; i < nch; ++i) {
        const int s = i & 1;
        const uint32_t Ab = base + (uint32_t)s * STAGE;
        const uint32_t Bb = Ab + A_BYTES;
        const bool pf = (i + 1 < nch);

        // one K=16 step
        auto compute_ks = [&](int ks) {
            uint32_t afr[4][4], bfr[4][2];
#pragma unroll
            for (int t = 0; t < 4; ++t) ldsm_x4(afr[t], Ab + swz(relA[t] + ks * 32));
#pragma unroll
            for (int u = 0; u < 4; ++u) ldsm_x2(bfr[u], Bb + swz(relB[u] + ks * 32));
#pragma unroll
            for (int t = 0; t < 4; ++t)
#pragma unroll
                for (int u = 0; u < 4; ++u)
                    mma_f16acc(cacc[t][u], afr[t], bfr[u]);
        };

        {
            float2 v[8];
            if (pf) loadA(c0 + i + 1, 0, v);
            compute_ks(0);
            if (pf) storeA(s ^ 1, 0, v);
        }
        {
            float2 v[8];
            if (pf) loadA(c0 + i + 1, 1, v);
            compute_ks(1);
            if (pf) storeA(s ^ 1, 1, v);
        }
        {
            float bF[16];
            if (pf) loadB(c0 + i + 1, bF);
            compute_ks(2);
            if (pf) storeB(s ^ 1, bF);
        }
        compute_ks(3);

        // per-chunk dump: f16 partial -> f32 master, reset f16 acc
#pragma unroll
        for (int t = 0; t < 4; ++t)
#pragma unroll
            for (int u = 0; u < 4; ++u) {
                const float2 lo = __half22float2(*(const __half2*)&cacc[t][u][0]);
                const float2 hi = __half22float2(*(const __half2*)&cacc[t][u][1]);
                facc[t][u][0] += lo.x; facc[t][u][1] += lo.y;
                facc[t][u][2] += hi.x; facc[t][u][3] += hi.y;
                cacc[t][u][0] = 0u;    cacc[t][u][1] = 0u;
            }

        __syncthreads();
    }

    // ---- epilogue: write split-K partials ----
    float* outp = g_partial + (size_t)sp * BS_ * HID;
#pragma unroll
    for (int t = 0; t < 4; ++t) {
        const int row0 = mt * MT + wm * 64 + t * 16 + (l >> 2);
#pragma unroll
        for (int u = 0; u < 4; ++u) {
            const int col = nt * NT + wn * 32 + u * 8 + (l & 3) * 2;
            float2 v0; v0.x = facc[t][u][0]; v0.y = facc[t][u][1];
            float2 v1; v1.x = facc[t][u][2]; v1.y = facc[t][u][3];
            *(float2*)(outp + (size_t)row0 * HID + col)       = v0;
            *(float2*)(outp + (size_t)(row0 + 8) * HID + col) = v1;
        }
    }
}

// ----------------------------------------------------------------------------
// W2 transpose: [512][129] -> W2T [129][512] (float4-loadable rows)
// grid (5, 16), block (32, 8)
// ----------------------------------------------------------------------------
__global__ void __launch_bounds__(256) transpose_w2_kernel(const float* __restrict__ W2)
{
    __shared__ float tile[32][33];
    const int j0 = blockIdx.x * 32;
    const int k0 = blockIdx.y * 32;

    // read W2[k][j] coalesced in j
#pragma unroll
    for (int i = threadIdx.y; i < 32; i += 8) {
        const int k = k0 + i;
        const int j = j0 + threadIdx.x;
        tile[i][threadIdx.x] = (j < ODIM) ? __ldg(W2 + (size_t)k * ODIM + j) : 0.0f;
    }
    __syncthreads();

    // write W2T[j][k] coalesced in k
    const int k = k0 + threadIdx.x;
#pragma unroll
    for (int i = threadIdx.y; i < 32; i += 8) {
        const int j = j0 + i;
        if (j < ODIM) g_w2t[(size_t)j * HID + k] = tile[threadIdx.x][i];
    }
}

// ----------------------------------------------------------------------------
// Kernel 2: reduce split-K partials + b1 + ReLU, then H @ W2T + b2.
// grid = 256 CTAs x 512 threads; 4 batch rows per CTA.
// ----------------------------------------------------------------------------
__global__ void __launch_bounds__(512) mlp2_kernel(
    const float* __restrict__ b1, const float* __restrict__ b2,
    float* __restrict__ out)
{
    __shared__ float h_s[4 * HID];   // 8 KB
    const int tid = threadIdx.x;
    const int row0 = blockIdx.x * 4;

    // Phase 1: 4 rows x 128 float4 = 512 float4 -> exactly 1 per thread
    {
        const int r  = tid >> 7;        // 0..3
        const int c4 = tid & 127;       // float4 column
        float4 s = __ldg((const float4*)b1 + c4);
#pragma unroll
        for (int sp = 0; sp < SPLIT; ++sp) {
            float4 p = *((const float4*)g_partial +
                         ((size_t)sp * BS_ + (row0 + r)) * (HID / 4) + c4);
            s.x += p.x; s.y += p.y; s.z += p.z; s.w += p.w;
        }
        float4* dst = (float4*)h_s + r * (HID / 4) + c4;
        dst->x = fmaxf(s.x, 0.0f); dst->y = fmaxf(s.y, 0.0f);
        dst->z = fmaxf(s.z, 0.0f); dst->w = fmaxf(s.w, 0.0f);
    }
    __syncthreads();

    // Phase 2: 4*129 = 516 dots; W2T rows read as float4 (L2-resident)
    for (int d = tid; d < 4 * ODIM; d += 512) {
        const int r = d / ODIM;
        const int j = d - r * ODIM;
        const float4* wp = (const float4*)(g_w2t + (size_t)j * HID);
        const float4* hp = (const float4*)(h_s + r * HID);
        float a0 = 0.f, a1 = 0.f, a2 = 0.f, a3 = 0.f;
#pragma unroll 8
        for (int k4 = 0; k4 < HID / 4; ++k4) {
            const float4 wv = __ldg(wp + k4);
            const float4 hv = hp[k4];
            a0 = fmaf(wv.x, hv.x, a0);
            a1 = fmaf(wv.y, hv.y, a1);
            a2 = fmaf(wv.z, hv.z, a2);
            a3 = fmaf(wv.w, hv.w, a3);
        }
        out[(size_t)row0 * ODIM + d] = (a0 + a1) + (a2 + a3) + __ldg(b2 + j);
    }
}

// ----------------------------------------------------------------------------
// Launch
// ----------------------------------------------------------------------------
extern "C" void kernel_launch(void* const* d_in, const int* in_sizes, int n_in,
                              void* d_out, int out_size) {
    const float* st  = (const float*)d_in[0];
    const float* at  = (const float*)d_in[1];
    const float* st1 = (const float*)d_in[2];
    const float* W1  = (const float*)d_in[3];
    const float* b1  = (const float*)d_in[4];
    const float* W2  = (const float*)d_in[5];
    const float* b2  = (const float*)d_in[6];
    float* out = (float*)d_out;

    cudaFuncSetAttribute(gemm1_kernel, cudaFuncAttributeMaxDynamicSharedMemorySize, SMEM_TOTAL);

    dim3 tgrid(5, 16);
    dim3 tblk(32, 8);
    transpose_w2_kernel<<<tgrid, tblk>>>(W2);
    gemm1_kernel<<<144, 512, SMEM_TOTAL>>>(st, at, st1, W1);
    mlp2_kernel<<<BS_ / 4, 512>>>(b1, b2, out);
}

// round 9
// speedup vs baseline: 2.1654x; 2.1654x over previous
#include <cuda_runtime.h>
#include <cuda_fp16.h>
#include <cstdint>

// ----------------------------------------------------------------------------
// Problem constants
// ----------------------------------------------------------------------------
#define BS_      1024
#define KTOT     33154
#define HID      512
#define ODIM     129
#define ST_LEN   16641
#define AT_LEN_  129
#define ST1_LEN  16384
#define B_AT     16641      /* st | at boundary   */
#define B_ST1    16770      /* at | st1 boundary  */

#define MT       256        /* CTA tile M (batch)  */
#define NT       128        /* CTA tile N (hidden) */
#define CHUNK    64         /* K per stage (fp16)  */
#define NCHUNK   519        /* ceil(33154/64)      */
#define SPLIT    9
#define CPS      58         /* ceil(519/9)         */

#define A_BYTES  (MT * CHUNK * 2)          /* 32768 */
#define B_BYTES  (NT * CHUNK * 2)          /* 16384 */
#define STAGE    (A_BYTES + B_BYTES)       /* 49152 */
#define SMEM_TOTAL (1024 + 2 * STAGE)      /* 99328 */

// split-K partials: 9 * 1024 * 512 * 4 = 18.9 MB
__device__ float g_partial[SPLIT * BS_ * HID];
// W2 transposed: [129][512] floats
__device__ float g_w2t[ODIM * HID];

// ----------------------------------------------------------------------------
// Helpers (plain-sm_103-safe PTX: ldmatrix / mma.sync fp16 / cvt.rn.f16)
// ----------------------------------------------------------------------------
__device__ __forceinline__ uint32_t smem_u32(const void* p) {
    uint32_t a;
    asm("{ .reg .u64 t; cvta.to.shared.u64 t, %1; cvt.u32.u64 %0, t; }" : "=r"(a) : "l"(p));
    return a;
}

__device__ __forceinline__ uint32_t swz(uint32_t off) {
    return off ^ ((off >> 3) & 0x70u);
}

__device__ __forceinline__ uint16_t f2h(float x) {
    uint16_t r;
    asm("cvt.rn.f16.f32 %0, %1;" : "=h"(r) : "f"(x));
    return r;
}

__device__ __forceinline__ uint32_t pack_f16x2(float x, float y) {
    uint32_t r;
    asm("cvt.rn.f16x2.f32 %0, %1, %2;" : "=r"(r) : "f"(y), "f"(x));
    return r;
}

__device__ __forceinline__ void ldsm_x4(uint32_t r[4], uint32_t addr) {
    asm volatile("ldmatrix.sync.aligned.m8n8.x4.shared.b16 {%0,%1,%2,%3}, [%4];"
                 : "=r"(r[0]), "=r"(r[1]), "=r"(r[2]), "=r"(r[3]) : "r"(addr));
}

__device__ __forceinline__ void ldsm_x2(uint32_t r[2], uint32_t addr) {
    asm volatile("ldmatrix.sync.aligned.m8n8.x2.shared.b16 {%0,%1}, [%2];"
                 : "=r"(r[0]), "=r"(r[1]) : "r"(addr));
}

// fp16 inputs, fp32 accumulators
__device__ __forceinline__ void mma_f16(float c[4], const uint32_t a[4], const uint32_t b[2]) {
    asm volatile(
        "mma.sync.aligned.m16n8k16.row.col.f32.f16.f16.f32 "
        "{%0,%1,%2,%3}, {%4,%5,%6,%7}, {%8,%9}, {%0,%1,%2,%3};"
        : "+f"(c[0]), "+f"(c[1]), "+f"(c[2]), "+f"(c[3])
        : "r"(a[0]), "r"(a[1]), "r"(a[2]), "r"(a[3]), "r"(b[0]), "r"(b[1]));
}

__device__ __forceinline__ void sts16(uint32_t addr, uint16_t v) {
    asm volatile("st.shared.u16 [%0], %1;" :: "r"(addr), "h"(v));
}
__device__ __forceinline__ void sts128(uint32_t addr, uint32_t v0, uint32_t v1, uint32_t v2, uint32_t v3) {
    asm volatile("st.shared.v4.b32 [%0], {%1,%2,%3,%4};" :: "r"(addr), "r"(v0), "r"(v1), "r"(v2), "r"(v3));
}

// ----------------------------------------------------------------------------
// GEMM1: H_partial = X @ W1, fp16 mma m16n8k16 (fp32 acc), split-K=9.
// grid = 144 CTAs = 4 nt x 4 mt x 9 split, 512 threads (16 warps).
// SMEM per stage: A [256 m][64 k] fp16, B [128 n][64 k] fp16; 128B rows, SW128.
// Warp tile 64(M) x 32(N).
// A staging: lane l covers k = l and k = l+32 (coalesced per row);
//            warp rg covers rows rg*16..rg*16+15, staged in 4 quarters of 4 rows.
// ----------------------------------------------------------------------------
__global__ void __launch_bounds__(512, 1) gemm1_kernel(
    const float* __restrict__ st, const float* __restrict__ at,
    const float* __restrict__ st1, const float* __restrict__ W1)
{
    extern __shared__ char smem_raw[];
    uint32_t base = smem_u32(smem_raw);
    base = (base + 1023u) & ~1023u;

    const int tid = threadIdx.x;
    const int l   = tid & 31;
    const int w   = tid >> 5;
    const int wm  = w >> 2;       // 0..3
    const int wn  = w & 3;        // 0..3

    const int bx = blockIdx.x;
    const int nt = bx & 3;
    const int mt = (bx >> 2) & 3;
    const int sp = bx >> 4;       // 0..8

    const int c0  = sp * CPS;
    int nch = NCHUNK - c0;
    if (nch > CPS) nch = CPS;

    // A staging: warp = row group (16 rows), lane = k column (l and l+32)
    const int am_base = mt * MT + w * 16;

    // B staging: n = tid&127, kg = tid>>7 -> 16 consecutive k values
    const int bn  = tid & 127;
    const int bkg = tid >> 7;                 // 0..3
    const float* W1p = W1 + (size_t)(nt * NT + bn);

    // resolve segment pointer for a global k (per-chunk hoist; uniform math)
    auto resolve = [&](int k, const float*& src, int& stride) {
        if (k < B_AT)        { src = st  + k;           stride = ST_LEN;  }
        else if (k < B_ST1)  { src = at  + (k - B_AT);  stride = AT_LEN_; }
        else if (k < KTOT)   { src = st1 + (k - B_ST1); stride = ST1_LEN; }
        else                 { src = 0;                 stride = 0;       }
    };

    // load quarter q (4 rows, 2 k's each = 8 floats)
    auto loadA = [&](const float* s0, int st0, const float* s1, int st1_,
                     int q, float v0[4], float v1[4]) {
        const int m0 = am_base + q * 4;
#pragma unroll
        for (int i = 0; i < 4; ++i) {
            v0[i] = s0 ? __ldg(s0 + (size_t)(m0 + i) * st0)  : 0.0f;
            v1[i] = s1 ? __ldg(s1 + (size_t)(m0 + i) * st1_) : 0.0f;
        }
    };
    auto storeA = [&](int s, int q, const float v0[4], const float v1[4]) {
        const uint32_t Ab = base + (uint32_t)s * STAGE;
#pragma unroll
        for (int i = 0; i < 4; ++i) {
            const uint32_t rowoff = (uint32_t)((w * 16 + q * 4 + i) * 128);
            sts16(Ab + swz(rowoff + l * 2),      f2h(v0[i]));
            sts16(Ab + swz(rowoff + 64 + l * 2), f2h(v1[i]));
        }
    };

    // B: 16 consecutive k values of column bn (transpose W1[k][n] -> smem[n][k])
    auto loadB = [&](int chunk, float bF[16]) {
        const int kb = chunk * CHUNK + bkg * 16;
#pragma unroll
        for (int j = 0; j < 16; ++j) {
            const int k = kb + j;
            bF[j] = (k < KTOT) ? __ldg(W1p + (size_t)k * HID) : 0.0f;
        }
    };
    auto storeB = [&](int s, const float bF[16]) {
        const uint32_t Bb = base + (uint32_t)s * STAGE + A_BYTES;
        uint32_t p0 = pack_f16x2(bF[0], bF[1]),  p1 = pack_f16x2(bF[2], bF[3]);
        uint32_t p2 = pack_f16x2(bF[4], bF[5]),  p3 = pack_f16x2(bF[6], bF[7]);
        sts128(Bb + swz((uint32_t)(bn * 128 + bkg * 32)), p0, p1, p2, p3);
        p0 = pack_f16x2(bF[8], bF[9]);   p1 = pack_f16x2(bF[10], bF[11]);
        p2 = pack_f16x2(bF[12], bF[13]); p3 = pack_f16x2(bF[14], bF[15]);
        sts128(Bb + swz((uint32_t)(bn * 128 + bkg * 32 + 16)), p0, p1, p2, p3);
    };

    // ---- fragment smem offsets (pre-swizzle, in-tile) ----
    uint32_t relA[4], relB[4];
#pragma unroll
    for (int t = 0; t < 4; ++t)
        relA[t] = (uint32_t)((wm * 64 + t * 16 + (l & 7) + ((l >> 3) & 1) * 8) * 128
                             + ((l >> 4) & 1) * 16);
    const int lm = l & 15;
#pragma unroll
    for (int u = 0; u < 4; ++u)
        relB[u] = (uint32_t)((wn * 32 + u * 8 + (lm & 7)) * 128 + ((lm >> 3) & 1) * 16);

    float acc[4][4][4];
#pragma unroll
    for (int t = 0; t < 4; ++t)
#pragma unroll
        for (int u = 0; u < 4; ++u)
#pragma unroll
            for (int j = 0; j < 4; ++j) acc[t][u][j] = 0.0f;

    // ---- prologue ----
    {
        const float *s0, *s1; int t0, t1;
        resolve(c0 * CHUNK + l,      s0, t0);
        resolve(c0 * CHUNK + 32 + l, s1, t1);
        float v0[4], v1[4]; float bF[16];
#pragma unroll
        for (int q = 0; q < 4; ++q) {
            loadA(s0, t0, s1, t1, q, v0, v1);
            storeA(0, q, v0, v1);
        }
        loadB(c0, bF); storeB(0, bF);
    }
    __syncthreads();

    // ---- main loop ----
    for (int i = 0; i < nch; ++i) {
        const int s = i & 1;
        const uint32_t Ab = base + (uint32_t)s * STAGE;
        const uint32_t Bb = Ab + A_BYTES;
        const bool pf = (i + 1 < nch);

        const float *s0 = 0, *s1 = 0; int t0 = 0, t1 = 0;
        if (pf) {
            resolve((c0 + i + 1) * CHUNK + l,      s0, t0);
            resolve((c0 + i + 1) * CHUNK + 32 + l, s1, t1);
        }

        // one K=16 step
        auto compute_ks = [&](int ks) {
            uint32_t afr[4][4], bfr[4][2];
#pragma unroll
            for (int t = 0; t < 4; ++t) ldsm_x4(afr[t], Ab + swz(relA[t] + ks * 32));
#pragma unroll
            for (int u = 0; u < 4; ++u) ldsm_x2(bfr[u], Bb + swz(relB[u] + ks * 32));
#pragma unroll
            for (int t = 0; t < 4; ++t)
#pragma unroll
                for (int u = 0; u < 4; ++u)
                    mma_f16(acc[t][u], afr[t], bfr[u]);
        };

        // quarters 0..2 interleaved with ks 0..2
#pragma unroll
        for (int q = 0; q < 3; ++q) {
            float v0[4], v1[4];
            if (pf) loadA(s0, t0, s1, t1, q, v0, v1);
            compute_ks(q);
            if (pf) storeA(s ^ 1, q, v0, v1);
        }
        // quarter 3 + B with ks 3
        {
            float v0[4], v1[4]; float bF[16];
            if (pf) { loadA(s0, t0, s1, t1, 3, v0, v1); loadB(c0 + i + 1, bF); }
            compute_ks(3);
            if (pf) { storeA(s ^ 1, 3, v0, v1); storeB(s ^ 1, bF); }
        }
        __syncthreads();
    }

    // ---- epilogue: write split-K partials ----
    float* outp = g_partial + (size_t)sp * BS_ * HID;
#pragma unroll
    for (int t = 0; t < 4; ++t) {
        const int row0 = mt * MT + wm * 64 + t * 16 + (l >> 2);
#pragma unroll
        for (int u = 0; u < 4; ++u) {
            const int col = nt * NT + wn * 32 + u * 8 + (l & 3) * 2;
            float2 v0; v0.x = acc[t][u][0]; v0.y = acc[t][u][1];
            float2 v1; v1.x = acc[t][u][2]; v1.y = acc[t][u][3];
            *(float2*)(outp + (size_t)row0 * HID + col)       = v0;
            *(float2*)(outp + (size_t)(row0 + 8) * HID + col) = v1;
        }
    }
}

// ----------------------------------------------------------------------------
// W2 transpose: [512][129] -> W2T [129][512] (float4-loadable rows)
// ----------------------------------------------------------------------------
__global__ void __launch_bounds__(256) transpose_w2_kernel(const float* __restrict__ W2)
{
    __shared__ float tile[32][33];
    const int j0 = blockIdx.x * 32;
    const int k0 = blockIdx.y * 32;

#pragma unroll
    for (int i = threadIdx.y; i < 32; i += 8) {
        const int k = k0 + i;
        const int j = j0 + threadIdx.x;
        tile[i][threadIdx.x] = (j < ODIM) ? __ldg(W2 + (size_t)k * ODIM + j) : 0.0f;
    }
    __syncthreads();

    const int k = k0 + threadIdx.x;
#pragma unroll
    for (int i = threadIdx.y; i < 32; i += 8) {
        const int j = j0 + i;
        if (j < ODIM) g_w2t[(size_t)j * HID + k] = tile[threadIdx.x][i];
    }
}

// ----------------------------------------------------------------------------
// Kernel 2: reduce split-K partials + b1 + ReLU, then H @ W2T + b2.
// grid = 256 CTAs x 512 threads; 4 batch rows per CTA.
// ----------------------------------------------------------------------------
__global__ void __launch_bounds__(512) mlp2_kernel(
    const float* __restrict__ b1, const float* __restrict__ b2,
    float* __restrict__ out)
{
    __shared__ float h_s[4 * HID];   // 8 KB
    const int tid = threadIdx.x;
    const int row0 = blockIdx.x * 4;

    // Phase 1: 4 rows x 128 float4 = 512 float4 -> exactly 1 per thread
    {
        const int r  = tid >> 7;
        const int c4 = tid & 127;
        float4 s = __ldg((const float4*)b1 + c4);
#pragma unroll
        for (int sp = 0; sp < SPLIT; ++sp) {
            float4 p = *((const float4*)g_partial +
                         ((size_t)sp * BS_ + (row0 + r)) * (HID / 4) + c4);
            s.x += p.x; s.y += p.y; s.z += p.z; s.w += p.w;
        }
        float4* dst = (float4*)h_s + r * (HID / 4) + c4;
        dst->x = fmaxf(s.x, 0.0f); dst->y = fmaxf(s.y, 0.0f);
        dst->z = fmaxf(s.z, 0.0f); dst->w = fmaxf(s.w, 0.0f);
    }
    __syncthreads();

    // Phase 2: 4*129 = 516 dots; W2T rows read as float4 (L2-resident)
    for (int d = tid; d < 4 * ODIM; d += 512) {
        const int r = d / ODIM;
        const int j = d - r * ODIM;
        const float4* wp = (const float4*)(g_w2t + (size_t)j * HID);
        const float4* hp = (const float4*)(h_s + r * HID);
        float a0 = 0.f, a1 = 0.f, a2 = 0.f, a3 = 0.f;
#pragma unroll 8
        for (int k4 = 0; k4 < HID / 4; ++k4) {
            const float4 wv = __ldg(wp + k4);
            const float4 hv = hp[k4];
            a0 = fmaf(wv.x, hv.x, a0);
            a1 = fmaf(wv.y, hv.y, a1);
            a2 = fmaf(wv.z, hv.z, a2);
            a3 = fmaf(wv.w, hv.w, a3);
        }
        out[(size_t)row0 * ODIM + d] = (a0 + a1) + (a2 + a3) + __ldg(b2 + j);
    }
}

// ----------------------------------------------------------------------------
// Launch
// ----------------------------------------------------------------------------
extern "C" void kernel_launch(void* const* d_in, const int* in_sizes, int n_in,
                              void* d_out, int out_size) {
    const float* st  = (const float*)d_in[0];
    const float* at  = (const float*)d_in[1];
    const float* st1 = (const float*)d_in[2];
    const float* W1  = (const float*)d_in[3];
    const float* b1  = (const float*)d_in[4];
    const float* W2  = (const float*)d_in[5];
    const float* b2  = (const float*)d_in[6];
    float* out = (float*)d_out;

    cudaFuncSetAttribute(gemm1_kernel, cudaFuncAttributeMaxDynamicSharedMemorySize, SMEM_TOTAL);

    dim3 tgrid(5, 16);
    dim3 tblk(32, 8);
    transpose_w2_kernel<<<tgrid, tblk>>>(W2);
    gemm1_kernel<<<144, 512, SMEM_TOTAL>>>(st, at, st1, W1);
    mlp2_kernel<<<BS_ / 4, 512>>>(b1, b2, out);
}